// round 1
// baseline (speedup 1.0000x reference)
#include <cuda_runtime.h>

// ScaledPLLayer: persistence landscape from precomputed PH pairs.
//   x:        [B=64, HW=4096] f32
//   birth_loc:[B, 128] i32, death_loc:[B, 128] i32, dim_idx:[B, 128] i32
//   out:      [B, 2, T=100, K=2] f32
//
// Per sample: birth[n]=x[bloc[n]], death[n]=x[dloc[n]],
//   fab(t,n) = max(min(t-birth, death-t), 0)
//   out[d,t,k] = max(top2_{n: dim==d}(fab with others masked to -1), 0)

#define B_     64
#define HW_    4096
#define NPH_   128
#define T_     100
#define K_     2

__global__ __launch_bounds__(128, 8)
void scaled_pl_kernel(const float* __restrict__ x,
                      const int*   __restrict__ bloc,
                      const int*   __restrict__ dloc,
                      const int*   __restrict__ didx,
                      float*       __restrict__ out) {
    __shared__ float s_birth[NPH_];
    __shared__ float s_death[NPH_];
    __shared__ int   s_dim[NPH_];

    const int b   = blockIdx.x;
    const int tid = threadIdx.x;

    // Phase 1: gather birth/death values for all 128 pairs of this sample.
    {
        const float* xb = x + b * HW_;
        const int n = tid;                       // blockDim == NPH_
        const int bi = bloc[b * NPH_ + n];
        const int di = dloc[b * NPH_ + n];
        s_birth[n] = __ldg(xb + bi);
        s_death[n] = __ldg(xb + di);
        s_dim[n]   = didx[b * NPH_ + n];
    }
    __syncthreads();

    // Phase 2: one thread per t; branchless top-2 for both dims at once.
    if (tid < T_) {
        const float t = (float)tid / (float)(T_ - 1);

        float m1d0 = -1.0f, m2d0 = -1.0f;   // top-2 for dim 0
        float m1d1 = -1.0f, m2d1 = -1.0f;   // top-2 for dim 1

        #pragma unroll 8
        for (int i = 0; i < NPH_; ++i) {
            const float fb  = s_birth[i];
            const float fd  = s_death[i];
            float fab = fminf(t - fb, fd - t);
            fab = fmaxf(fab, 0.0f);
            const bool is1 = (s_dim[i] != 0);
            const float v0 = is1 ? -1.0f : fab;
            const float v1 = is1 ? fab   : -1.0f;

            // top-2 insert: m2' = max(m2, min(m1, v)); m1' = max(m1, v)
            const float lo0 = fminf(m1d0, v0);
            m1d0 = fmaxf(m1d0, v0);
            m2d0 = fmaxf(m2d0, lo0);

            const float lo1 = fminf(m1d1, v1);
            m1d1 = fmaxf(m1d1, v1);
            m2d1 = fmaxf(m2d1, lo1);
        }

        // out layout: [B, 2, T, K] row-major
        float* o = out + ((size_t)b * 2 * T_ * K_) + tid * K_;
        o[0]             = fmaxf(m1d0, 0.0f);
        o[1]             = fmaxf(m2d0, 0.0f);
        o[T_ * K_ + 0]   = fmaxf(m1d1, 0.0f);
        o[T_ * K_ + 1]   = fmaxf(m2d1, 0.0f);
    }
}

extern "C" void kernel_launch(void* const* d_in, const int* in_sizes, int n_in,
                              void* d_out, int out_size) {
    const float* x    = (const float*)d_in[0];
    const int*   bloc = (const int*)  d_in[1];
    const int*   dloc = (const int*)  d_in[2];
    const int*   didx = (const int*)  d_in[3];
    float*       out  = (float*)      d_out;

    scaled_pl_kernel<<<B_, NPH_>>>(x, bloc, dloc, didx, out);
}

// round 2
// speedup vs baseline: 1.1100x; 1.1100x over previous
#include <cuda_runtime.h>

// ScaledPLLayer: persistence landscape from precomputed PH pairs.
//   x:        [B=64, HW=4096] f32
//   birth_loc:[B, 128] i32, death_loc:[B, 128] i32, dim_idx:[B, 128] i32
//   out:      [B, 2, T=100, K=2] f32
//
// out[b,d,t,k] = k-th largest over {max(min(t-birth_n, death_n-t), 0) : dim_n == d},
// clamped at 0 (equivalently: top-2 with 0-init over raw fab, masked pairs skipped).
//
// Strategy:
//  - grid = 2 CTAs per sample (t in [0,50) / [50,100)), block = 256.
//  - Gather phase: 128 threads fetch (birth, death, dim) and PARTITION pairs
//    into s_bd: dim-0 pairs at [0, n0), dim-1 pairs at [n0, 128).
//    Order within a region is nondeterministic but top-2 is order-invariant.
//  - Compute phase: quad of threads per t; each sub scans pairs i ≡ sub (mod 4)
//    (stride-4 keeps the n0 boundary balanced across subs). 6 ops per pair,
//    no masking, no clamp (0-init makes negative fab a no-op under max).
//  - 2-round shfl_xor top-2 merge within the quad; sub 0 writes 2×float2.

#define B_     64
#define HW_    4096
#define NPH_   128
#define T_     100
#define TPC_   50      // t-values per CTA

__global__ __launch_bounds__(256, 8)
void scaled_pl_kernel(const float* __restrict__ x,
                      const int*   __restrict__ bloc,
                      const int*   __restrict__ dloc,
                      const int*   __restrict__ didx,
                      float*       __restrict__ out) {
    __shared__ float2 s_bd[NPH_];
    __shared__ int    s_cnt[2];

    const int b     = blockIdx.x >> 1;
    const int thalf = blockIdx.x & 1;
    const int tid   = threadIdx.x;

    if (tid < 2) s_cnt[tid] = 0;
    __syncthreads();

    // ---- gather + partition ----
    if (tid < NPH_) {
        const float* xb = x + b * HW_;
        const int bi = bloc[b * NPH_ + tid];
        const int di = dloc[b * NPH_ + tid];
        const int dm = didx[b * NPH_ + tid];
        const float fb = __ldg(xb + bi);
        const float fd = __ldg(xb + di);
        int pos;
        if (dm == 0) pos = atomicAdd(&s_cnt[0], 1);
        else         pos = (NPH_ - 1) - atomicAdd(&s_cnt[1], 1);
        s_bd[pos] = make_float2(fb, fd);
    }
    __syncthreads();

    const int n0 = s_cnt[0];

    // ---- compute: quad (4 subs) per t ----
    const int tl  = tid >> 2;     // 0..63 (valid when < TPC_)
    const int sub = tid & 3;
    const int tg  = thalf * TPC_ + tl;
    const float t = (float)tg / (float)(T_ - 1);

    float m1a = 0.0f, m2a = 0.0f;   // dim 0 top-2
    float m1b = 0.0f, m2b = 0.0f;   // dim 1 top-2

    #pragma unroll 4
    for (int i = sub; i < n0; i += 4) {
        const float2 bd = s_bd[i];
        const float fab = fminf(t - bd.x, bd.y - t);
        const float lo  = fminf(m1a, fab);
        m1a = fmaxf(m1a, fab);
        m2a = fmaxf(m2a, lo);
    }
    const int start1 = n0 + ((sub - n0) & 3);
    #pragma unroll 4
    for (int i = start1; i < NPH_; i += 4) {
        const float2 bd = s_bd[i];
        const float fab = fminf(t - bd.x, bd.y - t);
        const float lo  = fminf(m1b, fab);
        m1b = fmaxf(m1b, fab);
        m2b = fmaxf(m2b, lo);
    }

    // ---- merge top-2 across the quad (all 256 threads participate) ----
    #pragma unroll
    for (int ofs = 1; ofs < 4; ofs <<= 1) {
        const float o1a = __shfl_xor_sync(0xffffffffu, m1a, ofs);
        const float o2a = __shfl_xor_sync(0xffffffffu, m2a, ofs);
        m2a = fmaxf(fmaxf(m2a, o2a), fminf(m1a, o1a));
        m1a = fmaxf(m1a, o1a);
        const float o1b = __shfl_xor_sync(0xffffffffu, m1b, ofs);
        const float o2b = __shfl_xor_sync(0xffffffffu, m2b, ofs);
        m2b = fmaxf(fmaxf(m2b, o2b), fminf(m1b, o1b));
        m1b = fmaxf(m1b, o1b);
    }

    if (sub == 0 && tl < TPC_) {
        float* o = out + (size_t)b * (2 * T_ * 2) + tg * 2;
        *reinterpret_cast<float2*>(o)             = make_float2(m1a, m2a);
        *reinterpret_cast<float2*>(o + T_ * 2)    = make_float2(m1b, m2b);
    }
}

extern "C" void kernel_launch(void* const* d_in, const int* in_sizes, int n_in,
                              void* d_out, int out_size) {
    const float* x    = (const float*)d_in[0];
    const int*   bloc = (const int*)  d_in[1];
    const int*   dloc = (const int*)  d_in[2];
    const int*   didx = (const int*)  d_in[3];
    float*       out  = (float*)      d_out;

    scaled_pl_kernel<<<2 * B_, 256>>>(x, bloc, dloc, didx, out);
}

// round 3
// speedup vs baseline: 1.1503x; 1.0363x over previous
#include <cuda_runtime.h>

// ScaledPLLayer: persistence landscape from precomputed PH pairs.
//   x:        [B=64, HW=4096] f32
//   birth_loc/death_loc/dim_idx: [B, 128] i32
//   out:      [B, 2, T=100, K=2] f32
//
// out[b,d,t,k] = k-th largest of {max(min(t-birth_n, death_n-t),0) : dim_n==d}
// == top-2 with 0-init over raw tent values of dim-d pairs (order-invariant).
//
// Structure:
//  - grid = 2 CTAs/sample (t-halves), block = 256.
//  - Warp 0: int4 index loads -> 8 gathers (full MLP) -> 4 ballot/popc passes
//    partitioning pairs into packed s0 (dim0) / s1 (dim1), padded to a
//    multiple of 8 with sentinel (4,-4) pairs (tent < 0 everywhere -> no-op).
//  - ONE __syncthreads.
//  - Quad of threads per t: each sub scans float4 groups (2 pairs/load) with
//    dual accumulator pairs; exact trip counts (n0r/8) so no bounds checks.
//  - 2-round shfl_xor top-2 merge; sub 0 stores 2x float2.

#define B_    64
#define HW_   4096
#define NPH_  128
#define T_    100
#define TPC_  50
#define FULL_ 0xffffffffu

__device__ __forceinline__ void top2_ins(float v, float& m1, float& m2) {
    m2 = fmaxf(m2, fminf(m1, v));
    m1 = fmaxf(m1, v);
}
// merge sorted pair (h1>=h2) into (m1>=m2)
__device__ __forceinline__ void top2_merge(float h1, float h2, float& m1, float& m2) {
    m2 = fmaxf(fminf(m1, h1), fmaxf(m2, h2));
    m1 = fmaxf(m1, h1);
}

__global__ __launch_bounds__(256, 4)
void scaled_pl_kernel(const float* __restrict__ x,
                      const int*   __restrict__ bloc,
                      const int*   __restrict__ dloc,
                      const int*   __restrict__ didx,
                      float*       __restrict__ out) {
    __shared__ __align__(16) float2 s0[136];
    __shared__ __align__(16) float2 s1[136];
    __shared__ int s_n0r, s_n1r;

    const int b     = blockIdx.x >> 1;
    const int thalf = blockIdx.x & 1;
    const int tid   = threadIdx.x;

    // ---- gather + ballot partition (warp 0 only) ----
    if (tid < 32) {
        const int lane = tid;
        const int4 bi = __ldg((const int4*)(bloc + b * NPH_) + lane);
        const int4 di = __ldg((const int4*)(dloc + b * NPH_) + lane);
        const int4 dm = __ldg((const int4*)(didx + b * NPH_) + lane);
        const float* xb = x + b * HW_;
        float fb[4], fd[4];
        fb[0] = __ldg(xb + bi.x); fb[1] = __ldg(xb + bi.y);
        fb[2] = __ldg(xb + bi.z); fb[3] = __ldg(xb + bi.w);
        fd[0] = __ldg(xb + di.x); fd[1] = __ldg(xb + di.y);
        fd[2] = __ldg(xb + di.z); fd[3] = __ldg(xb + di.w);
        int dmv[4] = { dm.x, dm.y, dm.z, dm.w };

        const unsigned lt = (1u << lane) - 1u;
        int off0 = 0, off1 = 0;
        #pragma unroll
        for (int p = 0; p < 4; ++p) {
            const bool is0 = (dmv[p] == 0);
            const unsigned mb = __ballot_sync(FULL_, is0);
            const int c0 = __popc(mb);
            float2* dst = is0 ? s0 : s1;
            const int pos = is0 ? (off0 + __popc(mb & lt))
                                : (off1 + __popc(~mb & lt));
            dst[pos] = make_float2(fb[p], fd[p]);
            off0 += c0;
            off1 += 32 - c0;
        }
        // pad both arrays to a multiple of 8 with sentinel pairs
        const int n0r = (off0 + 7) & ~7;
        const int n1r = (off1 + 7) & ~7;
        if (off0 + lane < n0r) s0[off0 + lane] = make_float2(4.0f, -4.0f);
        if (off1 + lane < n1r) s1[off1 + lane] = make_float2(4.0f, -4.0f);
        if (lane == 0) { s_n0r = n0r; s_n1r = n1r; }
    }
    __syncthreads();

    // ---- compute: quad per t, float4 loads (2 pairs), dual accumulators ----
    const int tl  = tid >> 2;            // 0..63
    const int sub = tid & 3;
    const int tg  = thalf * TPC_ + tl;
    const float t = (float)tg * (1.0f / (float)(T_ - 1));

    const int g0 = s_n0r >> 1;           // #float4 groups, multiple of 4
    const int g1 = s_n1r >> 1;
    const float4* v0 = (const float4*)s0;
    const float4* v1 = (const float4*)s1;

    float a1 = 0.f, a2 = 0.f, a3 = 0.f, a4 = 0.f;   // dim0 dual top-2
    float c1 = 0.f, c2 = 0.f, c3 = 0.f, c4 = 0.f;   // dim1 dual top-2

    #pragma unroll 2
    for (int g = sub; g < g0; g += 4) {
        const float4 p = v0[g];
        top2_ins(fminf(t - p.x, p.y - t), a1, a2);
        top2_ins(fminf(t - p.z, p.w - t), a3, a4);
    }
    #pragma unroll 2
    for (int g = sub; g < g1; g += 4) {
        const float4 p = v1[g];
        top2_ins(fminf(t - p.x, p.y - t), c1, c2);
        top2_ins(fminf(t - p.z, p.w - t), c3, c4);
    }
    top2_merge(a3, a4, a1, a2);
    top2_merge(c3, c4, c1, c2);

    // ---- quad merge via shfl_xor (all 256 threads participate) ----
    #pragma unroll
    for (int ofs = 1; ofs < 4; ofs <<= 1) {
        const float h1a = __shfl_xor_sync(FULL_, a1, ofs);
        const float h2a = __shfl_xor_sync(FULL_, a2, ofs);
        top2_merge(h1a, h2a, a1, a2);
        const float h1c = __shfl_xor_sync(FULL_, c1, ofs);
        const float h2c = __shfl_xor_sync(FULL_, c2, ofs);
        top2_merge(h1c, h2c, c1, c2);
    }

    if (sub == 0 && tl < TPC_) {
        float* o = out + (size_t)b * (2 * T_ * 2) + tg * 2;
        *reinterpret_cast<float2*>(o)          = make_float2(a1, a2);
        *reinterpret_cast<float2*>(o + T_ * 2) = make_float2(c1, c2);
    }
}

extern "C" void kernel_launch(void* const* d_in, const int* in_sizes, int n_in,
                              void* d_out, int out_size) {
    const float* x    = (const float*)d_in[0];
    const int*   bloc = (const int*)  d_in[1];
    const int*   dloc = (const int*)  d_in[2];
    const int*   didx = (const int*)  d_in[3];
    float*       out  = (float*)      d_out;

    scaled_pl_kernel<<<2 * B_, 256>>>(x, bloc, dloc, didx, out);
}